// round 12
// baseline (speedup 1.0000x reference)
#include <cuda_runtime.h>
#include <stdint.h>

// SpikeFP64Divider: gate-level FP64 restoring divider on rows of 64 {0,1} floats.
// Integer replica of the exact circuit semantics (13-bit modular exponent math,
// subnormal inputs treated as normals, mantissa-round carry-out structurally 0).
//
// R12: TMA bulk pipeline. 148 persistent blocks (1/SM), 128 threads, 128-row
// tiles. Loads: one cp.async.bulk per array per tile (replaces 512 LDGSTS
// issue slots); stores: STS into an out-stage + one bulk store. 2-stage
// double buffering on both in and out stages; mbarrier/expect_tx completion,
// wait_group.read for out-stage recycling. Pack/divide identical to R9.

#define SMEM_IN_A   0
#define SMEM_IN_B   65536
#define SMEM_OUT    131072
#define STAGE_SZ    32768
#define SMEM_TOTAL  196608

__global__ __launch_bounds__(128) void spike_div_kernel(
    const float* __restrict__ A, const float* __restrict__ B, float* __restrict__ O,
    int nTilesTotal)
{
    extern __shared__ char smem[];
    __shared__ uint64_t mbar[2];

    const unsigned FULL = 0xFFFFFFFFu;
    const int tid  = threadIdx.x;
    const int lane = tid & 31;
    const int warp = tid >> 5;

    const uint32_t smemBase = (uint32_t)__cvta_generic_to_shared(smem);
    const uint32_t mbarBase = (uint32_t)__cvta_generic_to_shared(mbar);

    if (tid == 0) {
        asm volatile("mbarrier.init.shared.b64 [%0], 1;" :: "r"(mbarBase)     : "memory");
        asm volatile("mbarrier.init.shared.b64 [%0], 1;" :: "r"(mbarBase + 8) : "memory");
    }
    __syncthreads();

    const int b  = blockIdx.x;
    const int gd = gridDim.x;
    const int nT = (nTilesTotal - b + gd - 1) / gd;    // my tile count

    // ---- issue one tile's loads (A 32KB + B 32KB) into stage j&1 (t0 only) ----
    auto issue_load = [&](int j) {
        const long long tile = (long long)b + (long long)j * gd;
        const int s = j & 1;
        const char* ga = (const char*)A + tile * 32768;
        const char* gb = (const char*)B + tile * 32768;
        const uint32_t mb = mbarBase + s * 8;
        asm volatile("mbarrier.arrive.expect_tx.shared.b64 _, [%0], %1;"
                     :: "r"(mb), "r"(65536u) : "memory");
        asm volatile("cp.async.bulk.shared::cta.global.mbarrier::complete_tx::bytes "
                     "[%0], [%1], %2, [%3];"
                     :: "r"(smemBase + SMEM_IN_A + s * STAGE_SZ), "l"(ga),
                        "r"(32768u), "r"(mb) : "memory");
        asm volatile("cp.async.bulk.shared::cta.global.mbarrier::complete_tx::bytes "
                     "[%0], [%1], %2, [%3];"
                     :: "r"(smemBase + SMEM_IN_B + s * STAGE_SZ), "l"(gb),
                        "r"(32768u), "r"(mb) : "memory");
    };

    if (tid == 0) {
        if (nT > 0) issue_load(0);
        if (nT > 1) issue_load(1);
    }

    int ph0 = 0, ph1 = 0;

    for (int j = 0; j < nT; j++) {
        const int s = j & 1;

        // ---- wait for tile j's data ----
        {
            const uint32_t mb = mbarBase + s * 8;
            const int phase = s ? ph1 : ph0;
            uint32_t done;
            do {
                asm volatile(
                    "{\n\t.reg .pred p;\n\t"
                    "mbarrier.try_wait.parity.acquire.cta.shared::cta.b64 p, [%1], %2, 0x989680;\n\t"
                    "selp.b32 %0, 1, 0, p;\n\t}"
                    : "=r"(done) : "r"(mb), "r"(phase) : "memory");
            } while (!done);
            if (s) ph1 ^= 1; else ph0 ^= 1;
        }

        // ---- Pack row (warp*32 + lane) straight from linear smem ----
        // chunk k (16B) = cols 4k..4k+3; rotated order (step+lane)&15 is
        // conflict-free per LDS.128 phase. {0,1}f flag = bit 29 of encoding.
        const char* inA = smem + SMEM_IN_A + s * STAGE_SZ + (warp * 32 + lane) * 256;
        const char* inB = smem + SMEM_IN_B + s * STAGE_SZ + (warp * 32 + lane) * 256;
        uint64_t wa = 0ull, wb = 0ull;
#pragma unroll
        for (int step = 0; step < 16; step++) {
            const int k = (step + lane) & 15;
            const uint4 va = *(const uint4*)(inA + k * 16);
            const uint32_t na = ((va.x >> 26) & 8u) | ((va.y >> 27) & 4u) |
                                ((va.z >> 28) & 2u) | ((va.w >> 29) & 1u);
            wa |= (uint64_t)na << (60 - 4 * k);
            const uint4 vb = *(const uint4*)(inB + k * 16);
            const uint32_t nb = ((vb.x >> 26) & 8u) | ((vb.y >> 27) & 4u) |
                                ((vb.z >> 28) & 2u) | ((vb.w >> 29) & 1u);
            wb |= (uint64_t)nb << (60 - 4 * k);
        }

        // ---- Circuit replica (one row per lane) ----
        const uint64_t M52 = 0x000FFFFFFFFFFFFFull;
        const uint32_t s_out = (uint32_t)((wa ^ wb) >> 63);
        const uint32_t ea = (uint32_t)(wa >> 52) & 0x7FFu;
        const uint32_t eb = (uint32_t)(wb >> 52) & 0x7FFu;
        const uint64_t ma = wa & M52;
        const uint64_t mb2 = wb & M52;

        const bool a_zero = (ea == 0u)     && (ma == 0ull);
        const bool b_zero = (eb == 0u)     && (mb2 == 0ull);
        const bool a_inf  = (ea == 0x7FFu) && (ma == 0ull);
        const bool b_inf  = (eb == 0x7FFu) && (mb2 == 0ull);
        const bool a_nan  = (ea == 0x7FFu) && (ma != 0ull);
        const bool b_nan  = (eb == 0x7FFu) && (mb2 != 0ull);

        const bool r_nan  = a_nan || b_nan || (a_zero && b_zero) || (a_inf && b_inf);
        const bool r_inf  = (!a_zero && b_zero) || (a_inf && !b_inf);
        const bool r_zero = (a_zero && !b_zero) || (!a_inf && b_inf);

        int exp13 = ((int)ea - (int)eb + 1023) & 8191;

        // Exact Q = floor(a * 2^56 / d) via 2 base-2^28 digits.
        const uint64_t a = (1ull << 53) | (ma << 1);
        const uint64_t d = (1ull << 53) | (mb2 << 1);
        const int64_t  ds = (int64_t)d;
        const double inv = 1.0 / (double)d;

        int64_t q1 = (int64_t)((double)a * 0x1p28 * inv);
        int64_t r1 = (int64_t)((a << 28) - (uint64_t)q1 * d);
        if (r1 < 0)   { q1--; r1 += ds; }
        if (r1 < 0)   { q1--; r1 += ds; }
        if (r1 >= ds) { q1++; r1 -= ds; }

        int64_t q2 = (int64_t)((double)r1 * 0x1p28 * inv);
        int64_t r2 = (int64_t)(((uint64_t)r1 << 28) - (uint64_t)q2 * d);
        if (r2 < 0)   { q2--; r2 += ds; }
        if (r2 < 0)   { q2--; r2 += ds; }
        if (r2 >= ds) { q2++; r2 -= ds; }

        const uint64_t Q = ((uint64_t)q1 << 28) + (uint64_t)q2;
        const bool remnz = (r2 != 0);

        const uint32_t q0 = (uint32_t)(Q >> 56) & 1u;
        uint64_t mant;
        uint32_t rnd;
        bool sticky;
        if (q0) {
            mant   = (Q >> 4) & M52;
            rnd    = (uint32_t)(Q >> 3) & 1u;
            sticky = ((Q & 7ull) != 0ull) || remnz;
        } else {
            mant   = (Q >> 3) & M52;
            rnd    = (uint32_t)(Q >> 2) & 1u;
            sticky = ((Q & 3ull) != 0ull) || remnz;
            exp13  = (exp13 - 1) & 8191;
        }

        // RNE; circuit's incrementer carry-out is structurally 0 (mask only).
        const uint32_t lsb = (uint32_t)mant & 1u;
        const uint32_t rup = (rnd && (sticky || lsb)) ? 1u : 0u;
        mant = (mant + (uint64_t)rup) & M52;

        const uint32_t exp_field = (uint32_t)exp13 & 0x7FFu;
        const bool ovf = ((exp13 >> 11) & 3) != 0;
        const bool unf = (((exp13 >> 12) & 1) != 0) || (exp13 == 0);

        const uint64_t sbit = (uint64_t)s_out << 63;
        uint64_t out;
        if (r_nan)       out = sbit | (0x7FFull << 52) | (1ull << 51);
        else if (r_inf)  out = sbit | (0x7FFull << 52);
        else if (r_zero) out = sbit;
        else if (ovf)    out = sbit | (0x7FFull << 52);
        else if (unf)    out = sbit;
        else             out = sbit | ((uint64_t)exp_field << 52) | mant;

        // ---- Recycle out-stage: tile j-2's bulk store must have read smem ----
        if (tid == 0) asm volatile("cp.async.bulk.wait_group.read 1;" ::: "memory");
        __syncthreads();   // also: all lanes done reading in-stage s

        // ---- Prefetch tile j+2 into the now-free in-stage s ----
        if (tid == 0 && j + 2 < nT) issue_load(j + 2);

        // ---- Unpack to out-stage via shuffle + STS.128 ----
        const uint32_t hi_o = (uint32_t)(out >> 32);   // cols 0..31
        const uint32_t lo_o = (uint32_t)out;           // cols 32..63
        char* outp = smem + SMEM_OUT + s * STAGE_SZ + warp * 8192;
        const int hsel = (lane >> 4) & 1;
        const bool use_lo = (lane & 8) != 0;
        const int nsh = 28 - 4 * (lane & 7);
#pragma unroll
        for (int kk = 0; kk < 16; kk++) {
            const int src = 2 * kk + hsel;             // owner lane = row in warp
            const uint32_t wh = __shfl_sync(FULL, hi_o, src);
            const uint32_t wl = __shfl_sync(FULL, lo_o, src);
            const uint32_t word = use_lo ? wl : wh;
            const uint32_t nib = (word >> nsh) & 0xFu;
            uint4 v;
            v.x = (nib & 8u) ? 0x3F800000u : 0u;
            v.y = (nib & 4u) ? 0x3F800000u : 0u;
            v.z = (nib & 2u) ? 0x3F800000u : 0u;
            v.w = (nib & 1u) ? 0x3F800000u : 0u;
            *(uint4*)(outp + (kk * 32 + lane) * 16) = v;
        }
        __syncthreads();

        // ---- One bulk store for the whole 32KB tile ----
        if (tid == 0) {
            const long long tile = (long long)b + (long long)j * gd;
            asm volatile("fence.proxy.async;" ::: "memory");
            asm volatile("cp.async.bulk.global.shared::cta.bulk_group [%0], [%1], %2;"
                         :: "l"((char*)O + tile * 32768),
                            "r"(smemBase + SMEM_OUT + s * STAGE_SZ),
                            "r"(32768u) : "memory");
            asm volatile("cp.async.bulk.commit_group;" ::: "memory");
        }
    }

    if (tid == 0) asm volatile("cp.async.bulk.wait_group 0;" ::: "memory");
}

extern "C" void kernel_launch(void* const* d_in, const int* in_sizes, int n_in,
                              void* d_out, int out_size) {
    const float* A = (const float*)d_in[0];
    const float* B = (const float*)d_in[1];
    float* O = (float*)d_out;
    const int rows   = in_sizes[0] / 64;     // 131072
    const int nTiles = rows / 128;           // 1024 tiles of 128 rows
    cudaFuncSetAttribute(spike_div_kernel,
                         cudaFuncAttributeMaxDynamicSharedMemorySize, SMEM_TOTAL);
    const int grid = nTiles < 148 ? nTiles : 148;
    spike_div_kernel<<<grid, 128, SMEM_TOTAL>>>(A, B, O, nTiles);
}

// round 13
// speedup vs baseline: 1.0107x; 1.0107x over previous
#include <cuda_runtime.h>
#include <stdint.h>

// SpikeFP64Divider: gate-level FP64 restoring divider on rows of 64 {0,1} floats.
// Integer replica of the exact circuit semantics (13-bit modular exponent math,
// subnormal inputs treated as normals, mantissa-round carry-out structurally 0).
//
// R13 = R9 (cp.async staging, per-lane row pack, exact base-2^28 division,
// shuffle+STG.128 unpack) with:
//  - A and B in separate cp.async commit groups: pack A overlaps B's flight.
//  - __syncwarp instead of __syncthreads (warps are fully independent).

static __device__ __forceinline__ void cp_async16(uint32_t dst, const void* src) {
    asm volatile("cp.async.cg.shared.global [%0], [%1], 16;" :: "r"(dst), "l"(src));
}

__global__ __launch_bounds__(64) void spike_div_kernel(
    const float* __restrict__ A, const float* __restrict__ B, float* __restrict__ O)
{
    // [warp][array][row][chunk] ; chunk swizzled by (row & 7). 32 KB total.
    __shared__ uint4 buf[2][2][32][16];

    const unsigned FULL = 0xFFFFFFFFu;
    const int lane = threadIdx.x & 31;
    const int warp = threadIdx.x >> 5;

    // Each warp owns 32 consecutive rows = 2048 floats = 512 uint4 chunks.
    const long long rowBase = ((long long)blockIdx.x * 2 + warp) * 32;
    const uint4* __restrict__ Ag = reinterpret_cast<const uint4*>(A) + rowBase * 16;
    const uint4* __restrict__ Bg = reinterpret_cast<const uint4*>(B) + rowBase * 16;

    // ---- Load phase: 16 cp.async per lane per array; separate groups ----
    // chunk g = i*32 + lane -> row r = g>>4, chunk k = g&15 ; dst chunk k^(r&7).
#pragma unroll
    for (int i = 0; i < 16; i++) {
        const int g = i * 32 + lane;
        const int r = g >> 4;
        const int k = (g & 15) ^ (r & 7);
        cp_async16((uint32_t)__cvta_generic_to_shared(&buf[warp][0][r][k]), Ag + g);
    }
    asm volatile("cp.async.commit_group;");          // group: A
#pragma unroll
    for (int i = 0; i < 16; i++) {
        const int g = i * 32 + lane;
        const int r = g >> 4;
        const int k = (g & 15) ^ (r & 7);
        cp_async16((uint32_t)__cvta_generic_to_shared(&buf[warp][1][r][k]), Bg + g);
    }
    asm volatile("cp.async.commit_group;");          // group: B

    // ---- Wait A only; pack A while B is still in flight ----
    asm volatile("cp.async.wait_group 1;" ::: "memory");
    __syncwarp();

    // Chunk k holds cols 4k..4k+3 ; col c -> bit 63-c ; {0,1}f flag = bit 29.
    uint32_t hiA = 0u, loA = 0u;
#pragma unroll
    for (int k = 0; k < 16; k++) {
        const int ks = k ^ (lane & 7);               // conflict-free per 8-lane phase
        const uint4 va = buf[warp][0][lane][ks];
        const uint32_t na = ((va.x >> 26) & 8u) | ((va.y >> 27) & 4u) |
                            ((va.z >> 28) & 2u) | ((va.w >> 29) & 1u);
        if (k < 8) hiA |= na << (28 - 4 * k);
        else       loA |= na << (28 - 4 * (k - 8));
    }

    // ---- Wait B; pack B ----
    asm volatile("cp.async.wait_group 0;" ::: "memory");
    __syncwarp();

    uint32_t hiB = 0u, loB = 0u;
#pragma unroll
    for (int k = 0; k < 16; k++) {
        const int ks = k ^ (lane & 7);
        const uint4 vb = buf[warp][1][lane][ks];
        const uint32_t nb = ((vb.x >> 26) & 8u) | ((vb.y >> 27) & 4u) |
                            ((vb.z >> 28) & 2u) | ((vb.w >> 29) & 1u);
        if (k < 8) hiB |= nb << (28 - 4 * k);
        else       loB |= nb << (28 - 4 * (k - 8));
    }

    const uint64_t wa = ((uint64_t)hiA << 32) | (uint64_t)loA;
    const uint64_t wb = ((uint64_t)hiB << 32) | (uint64_t)loB;

    // ---- Circuit replica (one row per lane, all 32 lanes productive) ----
    const uint64_t M52 = 0x000FFFFFFFFFFFFFull;
    const uint32_t s_out = (uint32_t)((wa ^ wb) >> 63);
    const uint32_t ea = (uint32_t)(wa >> 52) & 0x7FFu;
    const uint32_t eb = (uint32_t)(wb >> 52) & 0x7FFu;
    const uint64_t ma = wa & M52;
    const uint64_t mb = wb & M52;

    const bool a_zero = (ea == 0u)     && (ma == 0ull);
    const bool b_zero = (eb == 0u)     && (mb == 0ull);
    const bool a_inf  = (ea == 0x7FFu) && (ma == 0ull);
    const bool b_inf  = (eb == 0x7FFu) && (mb == 0ull);
    const bool a_nan  = (ea == 0x7FFu) && (ma != 0ull);
    const bool b_nan  = (eb == 0x7FFu) && (mb != 0ull);

    const bool r_nan  = a_nan || b_nan || (a_zero && b_zero) || (a_inf && b_inf);
    const bool r_inf  = (!a_zero && b_zero) || (a_inf && !b_inf);
    const bool r_zero = (a_zero && !b_zero) || (!a_inf && b_inf);

    // 13-bit modular exponent arithmetic, as the ripple circuits do.
    int exp13 = ((int)ea - (int)eb + 1023) & 8191;

    // ---- Exact Q = floor(a * 2^56 / d) via 2 base-2^28 digits ----
    const uint64_t a = (1ull << 53) | (ma << 1);
    const uint64_t d = (1ull << 53) | (mb << 1);
    const int64_t  ds = (int64_t)d;
    const double inv = 1.0 / (double)d;

    int64_t q1 = (int64_t)((double)a * 0x1p28 * inv);
    int64_t r1 = (int64_t)((a << 28) - (uint64_t)q1 * d);
    if (r1 < 0)   { q1--; r1 += ds; }
    if (r1 < 0)   { q1--; r1 += ds; }
    if (r1 >= ds) { q1++; r1 -= ds; }

    int64_t q2 = (int64_t)((double)r1 * 0x1p28 * inv);
    int64_t r2 = (int64_t)(((uint64_t)r1 << 28) - (uint64_t)q2 * d);
    if (r2 < 0)   { q2--; r2 += ds; }
    if (r2 < 0)   { q2--; r2 += ds; }
    if (r2 >= ds) { q2++; r2 -= ds; }

    const uint64_t Q = ((uint64_t)q1 << 28) + (uint64_t)q2;  // 57-bit quotient
    const bool remnz = (r2 != 0);

    // Normalize + guard/round/sticky (Q bit 56 = first quotient bit).
    const uint32_t q0 = (uint32_t)(Q >> 56) & 1u;
    uint64_t mant;
    uint32_t rnd;
    bool sticky;
    if (q0) {
        mant   = (Q >> 4) & M52;
        rnd    = (uint32_t)(Q >> 3) & 1u;
        sticky = ((Q & 7ull) != 0ull) || remnz;
    } else {
        mant   = (Q >> 3) & M52;
        rnd    = (uint32_t)(Q >> 2) & 1u;
        sticky = ((Q & 3ull) != 0ull) || remnz;
        exp13  = (exp13 - 1) & 8191;
    }

    // RNE; circuit's 53-bit incrementer carry-out is structurally 0:
    // mantissa overflow wraps to 0 WITHOUT exponent bump (mask only).
    const uint32_t lsb = (uint32_t)mant & 1u;
    const uint32_t rup = (rnd && (sticky || lsb)) ? 1u : 0u;
    mant = (mant + (uint64_t)rup) & M52;

    const uint32_t exp_field = (uint32_t)exp13 & 0x7FFu;
    const bool ovf = ((exp13 >> 11) & 3) != 0;
    const bool unf = (((exp13 >> 12) & 1) != 0) || (exp13 == 0);

    const uint64_t sbit = (uint64_t)s_out << 63;
    uint64_t out;
    if (r_nan)       out = sbit | (0x7FFull << 52) | (1ull << 51);
    else if (r_inf)  out = sbit | (0x7FFull << 52);
    else if (r_zero) out = sbit;
    else if (ovf)    out = sbit | (0x7FFull << 52);
    else if (unf)    out = sbit;
    else             out = sbit | ((uint64_t)exp_field << 52) | mant;

    // ---- Unpack: shuffle hi/lo from owner lane (lane r owns row r),
    // STG.128 float4. float4 i = k*32+lane: row 2k+(lane>>4), nib lane&15.
    const uint32_t hi_o = (uint32_t)(out >> 32);   // cols  0..31 (col c at bit 31-c)
    const uint32_t lo_o = (uint32_t)out;           // cols 32..63
    float4* __restrict__ O4 = reinterpret_cast<float4*>(O + rowBase * 64);
    const int hsel = (lane >> 4) & 1;              // which row of the pair I store
    const bool use_lo = (lane & 8) != 0;           // my 4 cols live in lo word?
    const int nsh = 28 - 4 * (lane & 7);           // nibble shift within word
#pragma unroll
    for (int k = 0; k < 16; k++) {
        const int src = 2 * k + hsel;              // row index = owner lane
        const uint32_t wh = __shfl_sync(FULL, hi_o, src);
        const uint32_t wl = __shfl_sync(FULL, lo_o, src);
        const uint32_t word = use_lo ? wl : wh;
        const uint32_t nib = (word >> nsh) & 0xFu;
        float4 v;
        v.x = __uint_as_float((nib & 8u) ? 0x3F800000u : 0u);
        v.y = __uint_as_float((nib & 4u) ? 0x3F800000u : 0u);
        v.z = __uint_as_float((nib & 2u) ? 0x3F800000u : 0u);
        v.w = __uint_as_float((nib & 1u) ? 0x3F800000u : 0u);
        O4[k * 32 + lane] = v;
    }
}

extern "C" void kernel_launch(void* const* d_in, const int* in_sizes, int n_in,
                              void* d_out, int out_size) {
    const float* A = (const float*)d_in[0];
    const float* B = (const float*)d_in[1];
    float* O = (float*)d_out;
    const int rows = in_sizes[0] / 64;       // 131072
    const int grid = rows / 64;              // 2048 blocks, 2 warps x 32 rows
    spike_div_kernel<<<grid, 64>>>(A, B, O);
}

// round 15
// speedup vs baseline: 1.2557x; 1.2424x over previous
#include <cuda_runtime.h>
#include <stdint.h>

// SpikeFP64Divider: gate-level FP64 restoring divider on rows of 64 {0,1} floats.
// Integer replica of the exact circuit semantics (13-bit modular exponent math,
// subnormal inputs treated as normals, mantissa-round carry-out structurally 0).
//
// R14 = R4 (champion: ballot-pack, per-lane divide, warp-autonomous) micro-tuned:
//  - 32-deep staged loads per batch (16 A + 16 B) with reg headroom
//    (launch_bounds(256,3), cap 84) so the loads actually stay in flight.
//  - store path = R9's verified 16x STG.128 (4x fewer store issues than R4).

__global__ __launch_bounds__(256, 3) void spike_div_kernel(
    const float* __restrict__ A, const float* __restrict__ B, float* __restrict__ O)
{
    const unsigned FULL = 0xFFFFFFFFu;
    const int lane = threadIdx.x & 31;
    const int warp = threadIdx.x >> 5;

    // Each warp owns 32 consecutive rows = 2048 floats.
    // Half-row k (0..63): row k/2, half k&1; element index k*32 + lane.
    const long long elemBase = (((long long)blockIdx.x * 8 + warp) * 32) * 64;
    const uint32_t* __restrict__ Au = reinterpret_cast<const uint32_t*>(A) + elemBase;
    const uint32_t* __restrict__ Bu = reinterpret_cast<const uint32_t*>(B) + elemBase;

    // ---- Pack: 4 batches of 32 staged loads (16 A + 16 B), then ballots ----
    // Ballot bit l = col (k&1)*32 + l of row k/2. Lane k/2 captures raw
    // ballots (hi = even k, lo = odd k); brev applied once at the end.
    uint32_t capA_hi = 0u, capA_lo = 0u, capB_hi = 0u, capB_lo = 0u;
#pragma unroll
    for (int k0 = 0; k0 < 64; k0 += 16) {
        uint32_t va[16], vb[16];
#pragma unroll
        for (int j = 0; j < 16; j++) va[j] = Au[(k0 + j) * 32 + lane];
#pragma unroll
        for (int j = 0; j < 16; j++) vb[j] = Bu[(k0 + j) * 32 + lane];
#pragma unroll
        for (int j = 0; j < 16; j++) {
            const int k = k0 + j;
            const uint32_t ba = __ballot_sync(FULL, va[j] != 0u);
            if (lane == (k >> 1)) { if (k & 1) capA_lo = ba; else capA_hi = ba; }
        }
#pragma unroll
        for (int j = 0; j < 16; j++) {
            const int k = k0 + j;
            const uint32_t bb = __ballot_sync(FULL, vb[j] != 0u);
            if (lane == (k >> 1)) { if (k & 1) capB_lo = bb; else capB_hi = bb; }
        }
    }
    // col c at bit 63-c: ballot bit l = col (half*32 + l) -> reverse each word.
    const uint64_t wa = ((uint64_t)__brev(capA_hi) << 32) | (uint64_t)__brev(capA_lo);
    const uint64_t wb = ((uint64_t)__brev(capB_hi) << 32) | (uint64_t)__brev(capB_lo);

    // ---- Circuit replica (one row per lane) ----
    const uint64_t M52 = 0x000FFFFFFFFFFFFFull;
    const uint32_t s_out = (uint32_t)((wa ^ wb) >> 63);
    const uint32_t ea = (uint32_t)(wa >> 52) & 0x7FFu;
    const uint32_t eb = (uint32_t)(wb >> 52) & 0x7FFu;
    const uint64_t ma = wa & M52;
    const uint64_t mb = wb & M52;

    const bool a_zero = (ea == 0u)     && (ma == 0ull);
    const bool b_zero = (eb == 0u)     && (mb == 0ull);
    const bool a_inf  = (ea == 0x7FFu) && (ma == 0ull);
    const bool b_inf  = (eb == 0x7FFu) && (mb == 0ull);
    const bool a_nan  = (ea == 0x7FFu) && (ma != 0ull);
    const bool b_nan  = (eb == 0x7FFu) && (mb != 0ull);

    const bool r_nan  = a_nan || b_nan || (a_zero && b_zero) || (a_inf && b_inf);
    const bool r_inf  = (!a_zero && b_zero) || (a_inf && !b_inf);
    const bool r_zero = (a_zero && !b_zero) || (!a_inf && b_inf);

    // 13-bit modular exponent arithmetic, as the ripple circuits do.
    int exp13 = ((int)ea - (int)eb + 1023) & 8191;

    // ---- Exact Q = floor(a * 2^56 / d) via 2 base-2^28 digits ----
    const uint64_t a = (1ull << 53) | (ma << 1);
    const uint64_t d = (1ull << 53) | (mb << 1);
    const int64_t  ds = (int64_t)d;
    const double inv = 1.0 / (double)d;

    int64_t q1 = (int64_t)((double)a * 0x1p28 * inv);
    int64_t r1 = (int64_t)((a << 28) - (uint64_t)q1 * d);
    if (r1 < 0)   { q1--; r1 += ds; }
    if (r1 < 0)   { q1--; r1 += ds; }
    if (r1 >= ds) { q1++; r1 -= ds; }

    int64_t q2 = (int64_t)((double)r1 * 0x1p28 * inv);
    int64_t r2 = (int64_t)(((uint64_t)r1 << 28) - (uint64_t)q2 * d);
    if (r2 < 0)   { q2--; r2 += ds; }
    if (r2 < 0)   { q2--; r2 += ds; }
    if (r2 >= ds) { q2++; r2 -= ds; }

    const uint64_t Q = ((uint64_t)q1 << 28) + (uint64_t)q2;  // 57-bit quotient
    const bool remnz = (r2 != 0);

    // Normalize + guard/round/sticky (Q bit 56 = first quotient bit).
    const uint32_t q0 = (uint32_t)(Q >> 56) & 1u;
    uint64_t mant;
    uint32_t rnd;
    bool sticky;
    if (q0) {
        mant   = (Q >> 4) & M52;
        rnd    = (uint32_t)(Q >> 3) & 1u;
        sticky = ((Q & 7ull) != 0ull) || remnz;
    } else {
        mant   = (Q >> 3) & M52;
        rnd    = (uint32_t)(Q >> 2) & 1u;
        sticky = ((Q & 3ull) != 0ull) || remnz;
        exp13  = (exp13 - 1) & 8191;
    }

    // RNE; circuit's 53-bit incrementer carry-out is structurally 0:
    // mantissa overflow wraps to 0 WITHOUT exponent bump (mask only).
    const uint32_t lsb = (uint32_t)mant & 1u;
    const uint32_t rup = (rnd && (sticky || lsb)) ? 1u : 0u;
    mant = (mant + (uint64_t)rup) & M52;

    const uint32_t exp_field = (uint32_t)exp13 & 0x7FFu;
    const bool ovf = ((exp13 >> 11) & 3) != 0;
    const bool unf = (((exp13 >> 12) & 1) != 0) || (exp13 == 0);

    const uint64_t sbit = (uint64_t)s_out << 63;
    uint64_t out;
    if (r_nan)       out = sbit | (0x7FFull << 52) | (1ull << 51);
    else if (r_inf)  out = sbit | (0x7FFull << 52);
    else if (r_zero) out = sbit;
    else if (ovf)    out = sbit | (0x7FFull << 52);
    else if (unf)    out = sbit;
    else             out = sbit | ((uint64_t)exp_field << 52) | mant;

    // ---- Unpack (R9-verified): shuffle hi/lo from owner lane, STG.128 ----
    // float4 i = k*32+lane: row 2k+(lane>>4), nibble lane&15 of that row.
    const uint32_t hi_o = (uint32_t)(out >> 32);   // cols  0..31 (col c at bit 31-c)
    const uint32_t lo_o = (uint32_t)out;           // cols 32..63
    float4* __restrict__ O4 = reinterpret_cast<float4*>(O + elemBase);
    const int hsel = (lane >> 4) & 1;              // which row of the pair I store
    const bool use_lo = (lane & 8) != 0;           // my 4 cols live in lo word?
    const int nsh = 28 - 4 * (lane & 7);           // nibble shift within word
#pragma unroll
    for (int k = 0; k < 16; k++) {
        const int src = 2 * k + hsel;              // row index = owner lane
        const uint32_t wh = __shfl_sync(FULL, hi_o, src);
        const uint32_t wl = __shfl_sync(FULL, lo_o, src);
        const uint32_t word = use_lo ? wl : wh;
        const uint32_t nib = (word >> nsh) & 0xFu;
        float4 v;
        v.x = __uint_as_float((nib & 8u) ? 0x3F800000u : 0u);
        v.y = __uint_as_float((nib & 4u) ? 0x3F800000u : 0u);
        v.z = __uint_as_float((nib & 2u) ? 0x3F800000u : 0u);
        v.w = __uint_as_float((nib & 1u) ? 0x3F800000u : 0u);
        O4[k * 32 + lane] = v;
    }
}

extern "C" void kernel_launch(void* const* d_in, const int* in_sizes, int n_in,
                              void* d_out, int out_size) {
    const float* A = (const float*)d_in[0];
    const float* B = (const float*)d_in[1];
    float* O = (float*)d_out;
    const int rows = in_sizes[0] / 64;       // 131072
    const int grid = rows / 256;             // 512 blocks, 8 warps x 32 rows
    spike_div_kernel<<<grid, 256>>>(A, B, O);
}